// round 11
// baseline (speedup 1.0000x reference)
#include <cuda_runtime.h>
#include <cuda_bf16.h>

#define NIDS    33                    // ids 0..32 (0 = background)
#define NBINS   1089                  // 33*33
#define THREADS 256                   // 8 warps; 4 CTAs/SM -> 32 warps/SM
#define NREP    16                    // replicated global histograms
#define NSTAGES 5                     // cp.async ring; 4 groups in flight
#define SMEM_STG (NSTAGES * THREADS * 16)          // one float4 ring: 20,480 B

// Scratch (zero at load; finalize block resets after every call)
__device__ int          g_rep[NREP][NBINS];
__device__ unsigned int g_ticket;

__global__ void __launch_bounds__(THREADS, 4)
fused_iou_kernel(const float4* __restrict__ p4, const float4* __restrict__ t4,
                 int n4,
                 const float* __restrict__ pf, const float* __restrict__ tf,
                 int n, float* __restrict__ out, int nblocks)
{
    __shared__ int    sh[NBINS];                       // exact int histogram
    __shared__ float4 stgP[NSTAGES * THREADS];         // staged pred
    __shared__ float4 stgT[NSTAGES * THREADS];         // staged true
    __shared__ float  psum[NIDS], tsum[NIDS], part[NIDS];
    __shared__ int    s_last;

    int tid = threadIdx.x;
    int gid    = blockIdx.x * THREADS + tid;
    int stride = gridDim.x * THREADS;

    // ---- issue stage: 2x 16B fire-and-forget cp.async into own slot ----
    auto issue = [&](int s, int idx) {
        if (idx < n4) {
            unsigned pa = (unsigned)__cvta_generic_to_shared(&stgP[s * THREADS + tid]);
            unsigned ta = (unsigned)__cvta_generic_to_shared(&stgT[s * THREADS + tid]);
            asm volatile("cp.async.cg.shared.global [%0], [%1], 16;" :: "r"(pa), "l"(p4 + idx));
            asm volatile("cp.async.cg.shared.global [%0], [%1], 16;" :: "r"(ta), "l"(t4 + idx));
        }
        asm volatile("cp.async.commit_group;");
    };

    // ---- prologue: 4 groups in flight immediately (DRAM saturates) ----
    issue(0, gid + 0 * stride);
    issue(1, gid + 1 * stride);
    issue(2, gid + 2 * stride);
    issue(3, gid + 3 * stride);

    // zero histogram while prefetches fly
    for (int b = tid; b < NBINS; b += THREADS) sh[b] = 0;
    __syncthreads();

    // ---- main loop: consume own slot, refill 4 ahead; no block sync needed ----
    for (int k = 0; gid + k * stride < n4; k++) {
        asm volatile("cp.async.wait_group %0;" :: "n"(NSTAGES - 2));  // stage k done
        int s = k % NSTAGES;
        float4 P = stgP[s * THREADS + tid];
        float4 T = stgT[s * THREADS + tid];
        issue((k + 4) % NSTAGES, gid + (k + 4) * stride);

        atomicAdd(&sh[(int)fmaf(P.x, 33.0f, T.x)], 1);   // bin = 33*p + t (exact fp32)
        atomicAdd(&sh[(int)fmaf(P.y, 33.0f, T.y)], 1);
        atomicAdd(&sh[(int)fmaf(P.z, 33.0f, T.z)], 1);
        atomicAdd(&sh[(int)fmaf(P.w, 33.0f, T.w)], 1);
    }
    asm volatile("cp.async.wait_group 0;");
    __syncthreads();

    // ---- flush block hist into replicated global hists ----
    int rep = blockIdx.x & (NREP - 1);
    for (int b = tid; b < NBINS; b += THREADS) {
        int v = sh[b];
        if (v) atomicAdd(&g_rep[rep][b], v);
    }
    __threadfence();

    // ---- ticket: last block finalizes ----
    if (tid == 0) {
        unsigned int t = atomicAdd(&g_ticket, 1u);
        s_last = (t == (unsigned int)(nblocks - 1));
    }
    __syncthreads();
    if (!s_last) return;

    for (int b = tid; b < NBINS; b += THREADS) {
        int s = 0;
        #pragma unroll
        for (int r = 0; r < NREP; r++) { s += g_rep[r][b]; g_rep[r][b] = 0; }
        sh[b] = s;
    }
    __syncthreads();
    if (tid == 0) {
        for (int k = n4 * 4; k < n; k++)                 // scalar tail (n % 4)
            sh[(int)fmaf(pf[k], 33.0f, tf[k])]++;
        g_ticket = 0u;
    }
    __syncthreads();

    if (tid < NIDS) {
        int s = 0;
        #pragma unroll
        for (int m = 0; m < NIDS; m++) s += sh[tid * NIDS + m];
        psum[tid] = (float)s;
    } else if (tid >= 64 && tid < 64 + NIDS) {
        int m = tid - 64, s = 0;
        #pragma unroll
        for (int nn = 0; nn < NIDS; nn++) s += sh[nn * NIDS + m];
        tsum[m] = (float)s;
    }
    __syncthreads();

    if (tid >= 1 && tid <= 32) {
        float pn = psum[tid];
        float max_iou = 0.0f;
        #pragma unroll
        for (int m = 1; m < NIDS; m++) {
            float inter = (float)sh[tid * NIDS + m];
            float uni   = pn + tsum[m] - inter;
            float iou   = (uni > 0.0f) ? (inter / uni) : 0.0f;
            max_iou = fmaxf(max_iou, iou);
        }
        part[tid] = 1.0f - max_iou;
    }
    __syncthreads();

    if (tid == 0) {
        float loss = 0.0f;
        for (int nn = 1; nn <= 32; nn++) loss += part[nn];
        double sp = 0.0, st = 0.0;                        // exact dummy term
        for (int id = 1; id < NIDS; id++) {
            sp += (double)id * (double)psum[id];
            st += (double)id * (double)tsum[id];
        }
        loss += (float)((sp + st) * 1e-12);
        out[0] = loss;
    }
}

extern "C" void kernel_launch(void* const* d_in, const int* in_sizes, int n_in,
                              void* d_out, int out_size) {
    const float* pred  = (const float*)d_in[0];
    const float* truem = (const float*)d_in[1];
    float* out = (float*)d_out;
    int n  = in_sizes[0];
    int n4 = n / 4;

    int sm_count = 148;
    cudaDeviceGetAttribute(&sm_count, cudaDevAttrMultiProcessorCount, 0);
    int blocks = sm_count * 4;   // 4 CTAs/SM x 8 warps = 32 warps/SM; ~45 KB smem/CTA

    fused_iou_kernel<<<blocks, THREADS>>>(
        (const float4*)pred, (const float4*)truem, n4,
        pred, truem, n, out, blocks);
}